// round 1
// baseline (speedup 1.0000x reference)
#include <cuda_runtime.h>
#include <cuda_fp16.h>
#include <cuda_fp8.h>
#include <math.h>

// ---------------- problem constants ----------------
#define B_   2
#define S_   2048
#define H_   2048
#define NH   16
#define HD   128
#define H3   (3 * H_)          // 6144
#define M1   (B_ * S_)         // 4096
#define PLANE (B_ * NH * S_ * HD)   // 8,388,608  (elements per q/k/v tensor)

// ---------------- scratch (device globals; no allocation allowed) ----------------
__device__ float         g_qkv[(size_t)M1 * H3];                 // 100.7 MB
__device__ unsigned char g_q8[(size_t)3 * PLANE];                // 25.2 MB  (fp8 e4m3 bytes; t=0:q,1:k,2:v)
__device__ float         g_scores[(size_t)B_ * NH * S_ * S_];    // 536.9 MB
__device__ float         g_attnout[(size_t)M1 * H_];             // 33.6 MB
__device__ unsigned int  g_absmax[3];
__device__ float         g_scales[3];

// ---------------- helpers ----------------
__device__ __forceinline__ float f8_to_f32(unsigned char v) {
    __half_raw hr = __nv_cvt_fp8_to_halfraw(v, __NV_E4M3);
    return __half2float(hr);
}

// ---------------- kernel 0: reset absmax (graph replays must be deterministic) ----
__global__ void zero_kernel() {
    if (threadIdx.x < 3) g_absmax[threadIdx.x] = 0u;
}

// ---------------- generic 64x64x32 SGEMM: C[M,N] = A[M,K] @ B[K,N] (+bias) -------
// All dims divisible by 64/64/32 in this problem. 256 threads, 4x4 per thread.
__global__ void sgemm64(const float* __restrict__ A, const float* __restrict__ Bm,
                        float* __restrict__ C, int M, int N, int K,
                        const float* __restrict__ bias)
{
    __shared__ float As[64][32];
    __shared__ float Bs[32][64];
    const int tid = threadIdx.x;
    const int tx  = tid & 15, ty = tid >> 4;
    const int m0  = blockIdx.y * 64;
    const int n0  = blockIdx.x * 64;

    float acc[4][4] = {};

    for (int k0 = 0; k0 < K; k0 += 32) {
        #pragma unroll
        for (int p = 0; p < 2; ++p) {               // A tile: 64x32 = 512 float4
            int lin = tid + p * 256;
            int r = lin >> 3, c4 = (lin & 7) << 2;
            *(float4*)&As[r][c4] =
                *(const float4*)&A[(size_t)(m0 + r) * K + k0 + c4];
        }
        #pragma unroll
        for (int p = 0; p < 2; ++p) {               // B tile: 32x64 = 512 float4
            int lin = tid + p * 256;
            int r = lin >> 4, c4 = (lin & 15) << 2;
            *(float4*)&Bs[r][c4] =
                *(const float4*)&Bm[(size_t)(k0 + r) * N + n0 + c4];
        }
        __syncthreads();

        #pragma unroll
        for (int kk = 0; kk < 32; ++kk) {
            float a0 = As[ty * 4 + 0][kk];
            float a1 = As[ty * 4 + 1][kk];
            float a2 = As[ty * 4 + 2][kk];
            float a3 = As[ty * 4 + 3][kk];
            float4 bv = *(float4*)&Bs[kk][tx * 4];
            acc[0][0] = fmaf(a0, bv.x, acc[0][0]); acc[0][1] = fmaf(a0, bv.y, acc[0][1]);
            acc[0][2] = fmaf(a0, bv.z, acc[0][2]); acc[0][3] = fmaf(a0, bv.w, acc[0][3]);
            acc[1][0] = fmaf(a1, bv.x, acc[1][0]); acc[1][1] = fmaf(a1, bv.y, acc[1][1]);
            acc[1][2] = fmaf(a1, bv.z, acc[1][2]); acc[1][3] = fmaf(a1, bv.w, acc[1][3]);
            acc[2][0] = fmaf(a2, bv.x, acc[2][0]); acc[2][1] = fmaf(a2, bv.y, acc[2][1]);
            acc[2][2] = fmaf(a2, bv.z, acc[2][2]); acc[2][3] = fmaf(a2, bv.w, acc[2][3]);
            acc[3][0] = fmaf(a3, bv.x, acc[3][0]); acc[3][1] = fmaf(a3, bv.y, acc[3][1]);
            acc[3][2] = fmaf(a3, bv.z, acc[3][2]); acc[3][3] = fmaf(a3, bv.w, acc[3][3]);
        }
        __syncthreads();
    }

    #pragma unroll
    for (int i = 0; i < 4; ++i) {
        int row = m0 + ty * 4 + i;
        #pragma unroll
        for (int j = 0; j < 4; ++j) {
            int col = n0 + tx * 4 + j;
            float v = acc[i][j];
            if (bias) v += bias[col];
            C[(size_t)row * N + col] = v;
        }
    }
}

// ---------------- kernel: per-tensor abs-max over q/k/v slices of qkv ------------
__global__ void absmax_kernel() {
    __shared__ unsigned int sm[3];
    if (threadIdx.x < 3) sm[threadIdx.x] = 0u;
    __syncthreads();

    const int gtid   = blockIdx.x * blockDim.x + threadIdx.x;
    const int stride = gridDim.x * blockDim.x;
    const int n2     = M1 * H_;           // elements per tensor slice (2^23)

    #pragma unroll
    for (int t = 0; t < 3; ++t) {
        unsigned int lm = 0u;
        for (int i = gtid; i < n2; i += stride) {
            int r = i >> 11;              // / 2048
            int c = i & 2047;
            float v = fabsf(g_qkv[(size_t)r * H3 + t * H_ + c]);
            unsigned int b = __float_as_uint(v);
            lm = (b > lm) ? b : lm;
        }
        atomicMax(&sm[t], lm);
    }
    __syncthreads();
    if (threadIdx.x < 3) atomicMax(&g_absmax[threadIdx.x], sm[threadIdx.x]);
}

__global__ void scales_kernel() {
    if (threadIdx.x < 3)
        g_scales[threadIdx.x] = __uint_as_float(g_absmax[threadIdx.x]) / 448.0f;
}

// ---------------- kernel: quantize to fp8 e4m3 in [t][b][h][s][d] layout ---------
__global__ void quant_kernel() {
    int idx = blockIdx.x * blockDim.x + threadIdx.x;
    if (idx >= 3 * PLANE) return;
    int t   = idx / PLANE;            // 0:q 1:k 2:v
    int rem = idx - t * PLANE;
    int d   = rem & 127;
    int s   = (rem >> 7) & 2047;
    int bh  = rem >> 18;              // 0..31
    int b   = bh >> 4, h = bh & 15;

    float v  = g_qkv[(size_t)(b * S_ + s) * H3 + t * H_ + h * HD + d];
    float sc = g_scales[t];
    g_q8[idx] = __nv_cvt_float_to_fp8(v / sc, __NV_SATFINITE, __NV_E4M3);
}

// ---------------- kernel: scores = (q8f @ k8f^T) * qs*ks/sqrt(hd) ---------------
__global__ void scores_kernel() {
    __shared__ float qs[64][33];
    __shared__ float ks[64][33];
    const int bh = blockIdx.z;
    const unsigned char* qp = g_q8 + (size_t)bh * (S_ * HD);
    const unsigned char* kp = g_q8 + (size_t)PLANE + (size_t)bh * (S_ * HD);
    const int i0 = blockIdx.y * 64;
    const int j0 = blockIdx.x * 64;
    const int tid = threadIdx.x;
    const int tx = tid & 15, ty = tid >> 4;

    float acc[4][4] = {};

    for (int kc = 0; kc < HD; kc += 32) {
        #pragma unroll
        for (int e = 0; e < 8; ++e) {     // 64x32 tile, 8 bytes/thread each
            int lin = tid + e * 256;
            int r = lin >> 5, c = lin & 31;
            qs[r][c] = f8_to_f32(qp[(i0 + r) * HD + kc + c]);
            ks[r][c] = f8_to_f32(kp[(j0 + r) * HD + kc + c]);
        }
        __syncthreads();

        #pragma unroll
        for (int kk = 0; kk < 32; ++kk) {
            float a0 = qs[ty * 4 + 0][kk], a1 = qs[ty * 4 + 1][kk];
            float a2 = qs[ty * 4 + 2][kk], a3 = qs[ty * 4 + 3][kk];
            float b0 = ks[tx * 4 + 0][kk], b1 = ks[tx * 4 + 1][kk];
            float b2 = ks[tx * 4 + 2][kk], b3 = ks[tx * 4 + 3][kk];
            acc[0][0] = fmaf(a0, b0, acc[0][0]); acc[0][1] = fmaf(a0, b1, acc[0][1]);
            acc[0][2] = fmaf(a0, b2, acc[0][2]); acc[0][3] = fmaf(a0, b3, acc[0][3]);
            acc[1][0] = fmaf(a1, b0, acc[1][0]); acc[1][1] = fmaf(a1, b1, acc[1][1]);
            acc[1][2] = fmaf(a1, b2, acc[1][2]); acc[1][3] = fmaf(a1, b3, acc[1][3]);
            acc[2][0] = fmaf(a2, b0, acc[2][0]); acc[2][1] = fmaf(a2, b1, acc[2][1]);
            acc[2][2] = fmaf(a2, b2, acc[2][2]); acc[2][3] = fmaf(a2, b3, acc[2][3]);
            acc[3][0] = fmaf(a3, b0, acc[3][0]); acc[3][1] = fmaf(a3, b1, acc[3][1]);
            acc[3][2] = fmaf(a3, b2, acc[3][2]); acc[3][3] = fmaf(a3, b3, acc[3][3]);
        }
        __syncthreads();
    }

    const float f = g_scales[0] * g_scales[1] / sqrtf(128.0f);
    float* out = g_scores + (size_t)bh * S_ * S_;
    #pragma unroll
    for (int i = 0; i < 4; ++i)
        #pragma unroll
        for (int j = 0; j < 4; ++j)
            out[(size_t)(i0 + ty * 4 + i) * S_ + j0 + tx * 4 + j] = acc[i][j] * f;
}

// ---------------- kernel: row softmax over 2048 keys ----------------------------
__global__ void softmax_kernel() {
    const int row = blockIdx.x;
    float* p = g_scores + (size_t)row * S_;
    const int tid = threadIdx.x;

    float v[8];
    float mx = -INFINITY;
    #pragma unroll
    for (int e = 0; e < 8; ++e) {
        v[e] = p[tid + e * 256];
        mx = fmaxf(mx, v[e]);
    }
    // block max
    #pragma unroll
    for (int o = 16; o; o >>= 1) mx = fmaxf(mx, __shfl_xor_sync(0xffffffffu, mx, o));
    __shared__ float smax[8];
    if ((tid & 31) == 0) smax[tid >> 5] = mx;
    __syncthreads();
    mx = smax[0];
    #pragma unroll
    for (int w = 1; w < 8; ++w) mx = fmaxf(mx, smax[w]);

    float sum = 0.0f;
    #pragma unroll
    for (int e = 0; e < 8; ++e) {
        v[e] = expf(v[e] - mx);
        sum += v[e];
    }
    #pragma unroll
    for (int o = 16; o; o >>= 1) sum += __shfl_xor_sync(0xffffffffu, sum, o);
    __shared__ float ssum[8];
    if ((tid & 31) == 0) ssum[tid >> 5] = sum;
    __syncthreads();
    sum = 0.0f;
    #pragma unroll
    for (int w = 0; w < 8; ++w) sum += ssum[w];

    #pragma unroll
    for (int e = 0; e < 8; ++e) p[tid + e * 256] = v[e] / sum;
}

// ---------------- kernel: out = (attn @ v8f) * v_scale, packed to [B,S,H] -------
__global__ void pv_kernel() {
    __shared__ float as[64][33];
    __shared__ float vs[32][128];
    const int bh = blockIdx.y;
    const int b = bh >> 4, h = bh & 15;
    const int i0 = blockIdx.x * 64;
    const float* ap = g_scores + (size_t)bh * S_ * S_;
    const unsigned char* vp = g_q8 + (size_t)2 * PLANE + (size_t)bh * (S_ * HD);
    const int tid = threadIdx.x;
    const int tx = tid & 15, ty = tid >> 4;

    float acc[4][8] = {};

    for (int kc = 0; kc < S_; kc += 32) {
        #pragma unroll
        for (int e = 0; e < 8; ++e) {     // attn tile 64x32
            int lin = tid + e * 256;
            int r = lin >> 5, c = lin & 31;
            as[r][c] = ap[(size_t)(i0 + r) * S_ + kc + c];
        }
        #pragma unroll
        for (int e = 0; e < 16; ++e) {    // v tile 32x128 (dequant)
            int lin = tid + e * 256;
            int r = lin >> 7, c = lin & 127;
            vs[r][c] = f8_to_f32(vp[(kc + r) * HD + c]);
        }
        __syncthreads();

        #pragma unroll
        for (int kk = 0; kk < 32; ++kk) {
            float a0 = as[ty * 4 + 0][kk], a1 = as[ty * 4 + 1][kk];
            float a2 = as[ty * 4 + 2][kk], a3 = as[ty * 4 + 3][kk];
            float4 bv0 = *(float4*)&vs[kk][tx * 8];
            float4 bv1 = *(float4*)&vs[kk][tx * 8 + 4];
            float bb[8] = {bv0.x, bv0.y, bv0.z, bv0.w, bv1.x, bv1.y, bv1.z, bv1.w};
            #pragma unroll
            for (int j = 0; j < 8; ++j) {
                acc[0][j] = fmaf(a0, bb[j], acc[0][j]);
                acc[1][j] = fmaf(a1, bb[j], acc[1][j]);
                acc[2][j] = fmaf(a2, bb[j], acc[2][j]);
                acc[3][j] = fmaf(a3, bb[j], acc[3][j]);
            }
        }
        __syncthreads();
    }

    const float vsc = g_scales[2];
    #pragma unroll
    for (int i = 0; i < 4; ++i) {
        int s = i0 + ty * 4 + i;
        #pragma unroll
        for (int j = 0; j < 8; ++j) {
            int col = tx * 8 + j;
            g_attnout[(size_t)(b * S_ + s) * H_ + h * HD + col] = acc[i][j] * vsc;
        }
    }
}

// ---------------- launch ----------------
extern "C" void kernel_launch(void* const* d_in, const int* in_sizes, int n_in,
                              void* d_out, int out_size)
{
    const float* x    = (const float*)d_in[0];
    const float* Wqkv = (const float*)d_in[1];
    const float* Wout = (const float*)d_in[2];
    const float* bout = (const float*)d_in[3];
    float* y = (float*)d_out;

    float *qkv_ptr = nullptr, *ao_ptr = nullptr;
    cudaGetSymbolAddress((void**)&qkv_ptr, g_qkv);
    cudaGetSymbolAddress((void**)&ao_ptr,  g_attnout);

    zero_kernel<<<1, 32>>>();

    // 1) qkv = x @ W_qkv   [4096,2048]@[2048,6144]
    sgemm64<<<dim3(H3 / 64, M1 / 64), 256>>>(x, Wqkv, qkv_ptr, M1, H3, H_, nullptr);

    // 2) per-tensor abs-max + scales
    absmax_kernel<<<1184, 256>>>();
    scales_kernel<<<1, 32>>>();

    // 3) quantize q/k/v to fp8 in head-major layout
    quant_kernel<<<(3 * PLANE) / 256, 256>>>();

    // 4) scores = q8f @ k8f^T * (qs*ks/sqrt(128))
    scores_kernel<<<dim3(S_ / 64, S_ / 64, B_ * NH), 256>>>();

    // 5) softmax over keys
    softmax_kernel<<<B_ * NH * S_, 256>>>();

    // 6) out = (attn @ v8f) * vs, packed into [B,S,H]
    pv_kernel<<<dim3(S_ / 64, B_ * NH), 256>>>();

    // 7) y = out @ W_out + b_out
    sgemm64<<<dim3(H_ / 64, M1 / 64), 256>>>(ao_ptr, Wout, y, M1, H_, H_, bout);
}

// round 2
// speedup vs baseline: 1.3486x; 1.3486x over previous
#include <cuda_runtime.h>
#include <cuda_fp16.h>
#include <cuda_fp8.h>
#include <math.h>

// ---------------- problem constants ----------------
#define B_   2
#define S_   2048
#define H_   2048
#define NH   16
#define HD   128
#define H3   (3 * H_)
#define M1   (B_ * S_)
#define PLANE (B_ * NH * S_ * HD)

// ---------------- scratch ----------------
__device__ float         g_qkv[(size_t)M1 * H3];
__device__ unsigned char g_q8[(size_t)3 * PLANE];
__device__ float         g_scores[(size_t)B_ * NH * S_ * S_];
__device__ float         g_attnout[(size_t)M1 * H_];
__device__ unsigned int  g_absmax[3];
__device__ float         g_scales[3];

__device__ __forceinline__ unsigned short f8_to_h(unsigned char v) {
    __half_raw hr = __nv_cvt_fp8_to_halfraw(v, __NV_E4M3);
    return hr.x;
}

__device__ __forceinline__ void mma_f16(float& d0, float& d1, float& d2, float& d3,
                                        unsigned a0, unsigned a1, unsigned a2, unsigned a3,
                                        unsigned b0, unsigned b1) {
    asm volatile("mma.sync.aligned.m16n8k16.row.col.f32.f16.f16.f32 "
                 "{%0,%1,%2,%3}, {%4,%5,%6,%7}, {%8,%9}, {%0,%1,%2,%3};"
                 : "+f"(d0), "+f"(d1), "+f"(d2), "+f"(d3)
                 : "r"(a0), "r"(a1), "r"(a2), "r"(a3), "r"(b0), "r"(b1));
}

__global__ void zero_kernel() {
    if (threadIdx.x < 3) g_absmax[threadIdx.x] = 0u;
}

// ---------------- fp32 SGEMM, 128x128 tile, 8x8 microtile, double-buffered ------
__global__ __launch_bounds__(256) void sgemm128(
    const float* __restrict__ A, const float* __restrict__ Bm,
    float* __restrict__ C, int M, int N, int K, const float* __restrict__ bias)
{
    __shared__ float As[2][16][136];   // transposed [k][m]
    __shared__ float Bs[2][16][136];   // [k][n]
    const int tid = threadIdx.x;
    const int tx = tid & 15, ty = tid >> 4;
    const int m0 = blockIdx.y * 128, n0 = blockIdx.x * 128;

    // A loader: 128x16 tile = 512 float4 ; lin: row=lin>>2, c4=(lin&3)*4
    // B loader: 16x128 tile = 512 float4 ; lin: row=lin>>5, c4=(lin&31)*4
    const int ar0 = (tid) >> 2,            ac0 = ((tid) & 3) << 2;
    const int ar1 = (tid + 256) >> 2,      ac1 = ((tid + 256) & 3) << 2;
    const int br0 = (tid) >> 5,            bc0 = ((tid) & 31) << 2;
    const int br1 = (tid + 256) >> 5,      bc1 = ((tid + 256) & 31) << 2;

    float acc[8][8] = {};
    float4 pa0, pa1, pb0, pb1;

    // preload tile 0
    pa0 = *(const float4*)&A[(size_t)(m0 + ar0) * K + ac0];
    pa1 = *(const float4*)&A[(size_t)(m0 + ar1) * K + ac1];
    pb0 = *(const float4*)&Bm[(size_t)(br0) * N + n0 + bc0];
    pb1 = *(const float4*)&Bm[(size_t)(br1) * N + n0 + bc1];
    As[0][ac0 + 0][ar0] = pa0.x; As[0][ac0 + 1][ar0] = pa0.y;
    As[0][ac0 + 2][ar0] = pa0.z; As[0][ac0 + 3][ar0] = pa0.w;
    As[0][ac1 + 0][ar1] = pa1.x; As[0][ac1 + 1][ar1] = pa1.y;
    As[0][ac1 + 2][ar1] = pa1.z; As[0][ac1 + 3][ar1] = pa1.w;
    *(float4*)&Bs[0][br0][bc0] = pb0;
    *(float4*)&Bs[0][br1][bc1] = pb1;
    __syncthreads();

    const int T = K >> 4;
    int buf = 0;
    for (int t = 0; t < T; ++t) {
        if (t + 1 < T) {
            int k0 = (t + 1) << 4;
            pa0 = *(const float4*)&A[(size_t)(m0 + ar0) * K + k0 + ac0];
            pa1 = *(const float4*)&A[(size_t)(m0 + ar1) * K + k0 + ac1];
            pb0 = *(const float4*)&Bm[(size_t)(k0 + br0) * N + n0 + bc0];
            pb1 = *(const float4*)&Bm[(size_t)(k0 + br1) * N + n0 + bc1];
        }
        #pragma unroll
        for (int kk = 0; kk < 16; ++kk) {
            float4 a0 = *(float4*)&As[buf][kk][ty * 8];
            float4 a1 = *(float4*)&As[buf][kk][ty * 8 + 4];
            float4 b0 = *(float4*)&Bs[buf][kk][tx * 8];
            float4 b1 = *(float4*)&Bs[buf][kk][tx * 8 + 4];
            float av[8] = {a0.x, a0.y, a0.z, a0.w, a1.x, a1.y, a1.z, a1.w};
            float bv[8] = {b0.x, b0.y, b0.z, b0.w, b1.x, b1.y, b1.z, b1.w};
            #pragma unroll
            for (int i = 0; i < 8; ++i)
                #pragma unroll
                for (int j = 0; j < 8; ++j)
                    acc[i][j] = fmaf(av[i], bv[j], acc[i][j]);
        }
        if (t + 1 < T) {
            __syncthreads();
            int nb = buf ^ 1;
            As[nb][ac0 + 0][ar0] = pa0.x; As[nb][ac0 + 1][ar0] = pa0.y;
            As[nb][ac0 + 2][ar0] = pa0.z; As[nb][ac0 + 3][ar0] = pa0.w;
            As[nb][ac1 + 0][ar1] = pa1.x; As[nb][ac1 + 1][ar1] = pa1.y;
            As[nb][ac1 + 2][ar1] = pa1.z; As[nb][ac1 + 3][ar1] = pa1.w;
            *(float4*)&Bs[nb][br0][bc0] = pb0;
            *(float4*)&Bs[nb][br1][bc1] = pb1;
            __syncthreads();
            buf = nb;
        }
    }

    #pragma unroll
    for (int i = 0; i < 8; ++i) {
        int row = m0 + ty * 8 + i;
        float4 o0, o1;
        o0.x = acc[i][0]; o0.y = acc[i][1]; o0.z = acc[i][2]; o0.w = acc[i][3];
        o1.x = acc[i][4]; o1.y = acc[i][5]; o1.z = acc[i][6]; o1.w = acc[i][7];
        if (bias) {
            int c = n0 + tx * 8;
            o0.x += bias[c + 0]; o0.y += bias[c + 1]; o0.z += bias[c + 2]; o0.w += bias[c + 3];
            o1.x += bias[c + 4]; o1.y += bias[c + 5]; o1.z += bias[c + 6]; o1.w += bias[c + 7];
        }
        *(float4*)&C[(size_t)row * N + n0 + tx * 8] = o0;
        *(float4*)&C[(size_t)row * N + n0 + tx * 8 + 4] = o1;
    }
}

// ---------------- abs-max / scales / quant (unchanged) ----------------
__global__ void absmax_kernel() {
    __shared__ unsigned int sm[3];
    if (threadIdx.x < 3) sm[threadIdx.x] = 0u;
    __syncthreads();
    const int gtid = blockIdx.x * blockDim.x + threadIdx.x;
    const int stride = gridDim.x * blockDim.x;
    const int n2 = M1 * H_;
    #pragma unroll
    for (int t = 0; t < 3; ++t) {
        unsigned int lm = 0u;
        for (int i = gtid; i < n2; i += stride) {
            int r = i >> 11, c = i & 2047;
            unsigned int b = __float_as_uint(fabsf(g_qkv[(size_t)r * H3 + t * H_ + c]));
            lm = (b > lm) ? b : lm;
        }
        atomicMax(&sm[t], lm);
    }
    __syncthreads();
    if (threadIdx.x < 3) atomicMax(&g_absmax[threadIdx.x], sm[threadIdx.x]);
}

__global__ void scales_kernel() {
    if (threadIdx.x < 3)
        g_scales[threadIdx.x] = __uint_as_float(g_absmax[threadIdx.x]) / 448.0f;
}

__global__ void quant_kernel() {
    int idx = blockIdx.x * blockDim.x + threadIdx.x;
    if (idx >= 3 * PLANE) return;
    int t = idx / PLANE;
    int rem = idx - t * PLANE;
    int d = rem & 127;
    int s = (rem >> 7) & 2047;
    int bh = rem >> 18;
    int b = bh >> 4, h = bh & 15;
    float v = g_qkv[(size_t)(b * S_ + s) * H3 + t * H_ + h * HD + d];
    g_q8[idx] = __nv_cvt_float_to_fp8(v / g_scales[t], __NV_SATFINITE, __NV_E4M3);
}

// ---------------- scores via fp16 MMA (exact: e4m3 subset of fp16) --------------
// block tile 128(q) x 128(k); K=HD=128 in 2 chunks of 64; 8 warps (2x4), warp 64x32
__global__ __launch_bounds__(256) void scores_mma_kernel() {
    __shared__ __half qs[128][72];   // row stride 36 words (36%32=4 -> conflict-free frags)
    __shared__ __half ks[128][72];
    const int tid = threadIdx.x;
    const int wid = tid >> 5, lane = tid & 31;
    const int g = lane >> 2, tig = lane & 3;
    const int bh = blockIdx.z;
    const int m0 = blockIdx.y * 128, n0 = blockIdx.x * 128;
    const unsigned char* qp = g_q8 + (size_t)bh * (S_ * HD);
    const unsigned char* kp = g_q8 + (size_t)PLANE + (size_t)bh * (S_ * HD);
    const int wm = (wid & 1) * 64, wn = (wid >> 1) * 32;

    float acc[4][4][4] = {};

    for (int ch = 0; ch < 2; ++ch) {
        const int coff = ch * 64;
        // fill 128 rows x 64 bytes each for q and k: 2048 u32 / 256 thr = 8 each
        #pragma unroll
        for (int p = 0; p < 8; ++p) {
            int lin = tid + p * 256;            // u32 index
            int r = lin >> 4, c = (lin & 15) << 2;   // byte col within chunk
            unsigned int qv = *(const unsigned int*)&qp[(size_t)(m0 + r) * HD + coff + c];
            unsigned int kv = *(const unsigned int*)&kp[(size_t)(n0 + r) * HD + coff + c];
            unsigned int q01 = (unsigned)f8_to_h(qv & 0xff) | ((unsigned)f8_to_h((qv >> 8) & 0xff) << 16);
            unsigned int q23 = (unsigned)f8_to_h((qv >> 16) & 0xff) | ((unsigned)f8_to_h(qv >> 24) << 16);
            unsigned int k01 = (unsigned)f8_to_h(kv & 0xff) | ((unsigned)f8_to_h((kv >> 8) & 0xff) << 16);
            unsigned int k23 = (unsigned)f8_to_h((kv >> 16) & 0xff) | ((unsigned)f8_to_h(kv >> 24) << 16);
            *(unsigned int*)&qs[r][c + 0] = q01;
            *(unsigned int*)&qs[r][c + 2] = q23;
            *(unsigned int*)&ks[r][c + 0] = k01;
            *(unsigned int*)&ks[r][c + 2] = k23;
        }
        __syncthreads();

        #pragma unroll
        for (int kstep = 0; kstep < 4; ++kstep) {
            const int kb = kstep * 16;
            unsigned a[4][4], b[4][2];
            #pragma unroll
            for (int mi = 0; mi < 4; ++mi) {
                int r = wm + mi * 16 + g;
                a[mi][0] = *(unsigned*)&qs[r][kb + 2 * tig];
                a[mi][1] = *(unsigned*)&qs[r + 8][kb + 2 * tig];
                a[mi][2] = *(unsigned*)&qs[r][kb + 2 * tig + 8];
                a[mi][3] = *(unsigned*)&qs[r + 8][kb + 2 * tig + 8];
            }
            #pragma unroll
            for (int ni = 0; ni < 4; ++ni) {
                int r = wn + ni * 8 + g;
                b[ni][0] = *(unsigned*)&ks[r][kb + 2 * tig];
                b[ni][1] = *(unsigned*)&ks[r][kb + 2 * tig + 8];
            }
            #pragma unroll
            for (int mi = 0; mi < 4; ++mi)
                #pragma unroll
                for (int ni = 0; ni < 4; ++ni)
                    mma_f16(acc[mi][ni][0], acc[mi][ni][1], acc[mi][ni][2], acc[mi][ni][3],
                            a[mi][0], a[mi][1], a[mi][2], a[mi][3], b[ni][0], b[ni][1]);
        }
        __syncthreads();
    }

    const float f = g_scales[0] * g_scales[1] * 0.08838834764831843f; // 1/sqrt(128)
    float* out = g_scores + (size_t)bh * S_ * S_;
    #pragma unroll
    for (int mi = 0; mi < 4; ++mi) {
        int r = m0 + wm + mi * 16 + g;
        #pragma unroll
        for (int ni = 0; ni < 4; ++ni) {
            int c = n0 + wn + ni * 8 + 2 * tig;
            float2 v0 = {acc[mi][ni][0] * f, acc[mi][ni][1] * f};
            float2 v1 = {acc[mi][ni][2] * f, acc[mi][ni][3] * f};
            *(float2*)&out[(size_t)r * S_ + c] = v0;
            *(float2*)&out[(size_t)(r + 8) * S_ + c] = v1;
        }
    }
}

// ---------------- softmax (unchanged) ----------------
__global__ void softmax_kernel() {
    const int row = blockIdx.x;
    float* p = g_scores + (size_t)row * S_;
    const int tid = threadIdx.x;
    float v[8];
    float mx = -INFINITY;
    #pragma unroll
    for (int e = 0; e < 8; ++e) { v[e] = p[tid + e * 256]; mx = fmaxf(mx, v[e]); }
    #pragma unroll
    for (int o = 16; o; o >>= 1) mx = fmaxf(mx, __shfl_xor_sync(0xffffffffu, mx, o));
    __shared__ float smax[8];
    if ((tid & 31) == 0) smax[tid >> 5] = mx;
    __syncthreads();
    mx = smax[0];
    #pragma unroll
    for (int w = 1; w < 8; ++w) mx = fmaxf(mx, smax[w]);
    float sum = 0.0f;
    #pragma unroll
    for (int e = 0; e < 8; ++e) { v[e] = expf(v[e] - mx); sum += v[e]; }
    #pragma unroll
    for (int o = 16; o; o >>= 1) sum += __shfl_xor_sync(0xffffffffu, sum, o);
    __shared__ float ssum[8];
    if ((tid & 31) == 0) ssum[tid >> 5] = sum;
    __syncthreads();
    sum = 0.0f;
    #pragma unroll
    for (int w = 0; w < 8; ++w) sum += ssum[w];
    #pragma unroll
    for (int e = 0; e < 8; ++e) p[tid + e * 256] = v[e] / sum;
}

// ---------------- PV via fp16 MMA: block 64(q) x 128(d), Ktile 32 ---------------
__global__ __launch_bounds__(256) void pv_mma_kernel() {
    __shared__ __half ps[64][72];    // attn probs (fp16-rounded), row stride 36 words
    __shared__ __half vt[128][72];   // v transposed [d][k], row stride 36 words
    const int tid = threadIdx.x;
    const int wid = tid >> 5, lane = tid & 31;
    const int g = lane >> 2, tig = lane & 3;
    const int bh = blockIdx.y;
    const int b = bh >> 4, h = bh & 15;
    const int i0 = blockIdx.x * 64;
    const float* ap = g_scores + (size_t)bh * S_ * S_;
    const unsigned char* vp = g_q8 + (size_t)2 * PLANE + (size_t)bh * (S_ * HD);
    const int wm = (wid & 1) * 32, wn = (wid >> 1) * 32;

    float acc[2][4][4] = {};

    for (int kc = 0; kc < S_; kc += 32) {
        // fill ps: 64 x 32 f32 -> half : 2048 f32 / 256 = 8 each
        #pragma unroll
        for (int p = 0; p < 2; ++p) {
            int lin = tid + p * 256;            // float4 index over 512
            int r = lin >> 3, c = (lin & 7) << 2;
            float4 vv = *(const float4*)&ap[(size_t)(i0 + r) * S_ + kc + c];
            __half2 h0 = __floats2half2_rn(vv.x, vv.y);
            __half2 h1 = __floats2half2_rn(vv.z, vv.w);
            *(__half2*)&ps[r][c + 0] = h0;
            *(__half2*)&ps[r][c + 2] = h1;
        }
        // fill vt (transposed): 32 k-rows x 128 d bytes = 1024 u32 / 256 = 4 each
        #pragma unroll
        for (int p = 0; p < 4; ++p) {
            int lin = tid + p * 256;
            int r = lin >> 5, c = (lin & 31) << 2;   // k-row r, d col c..c+3
            unsigned int vv = *(const unsigned int*)&vp[(size_t)(kc + r) * HD + c];
            vt[c + 0][r] = __ushort_as_half(f8_to_h(vv & 0xff));
            vt[c + 1][r] = __ushort_as_half(f8_to_h((vv >> 8) & 0xff));
            vt[c + 2][r] = __ushort_as_half(f8_to_h((vv >> 16) & 0xff));
            vt[c + 3][r] = __ushort_as_half(f8_to_h(vv >> 24));
        }
        __syncthreads();

        #pragma unroll
        for (int kstep = 0; kstep < 2; ++kstep) {
            const int kb = kstep * 16;
            unsigned a[2][4], bfr[4][2];
            #pragma unroll
            for (int mi = 0; mi < 2; ++mi) {
                int r = wm + mi * 16 + g;
                a[mi][0] = *(unsigned*)&ps[r][kb + 2 * tig];
                a[mi][1] = *(unsigned*)&ps[r + 8][kb + 2 * tig];
                a[mi][2] = *(unsigned*)&ps[r][kb + 2 * tig + 8];
                a[mi][3] = *(unsigned*)&ps[r + 8][kb + 2 * tig + 8];
            }
            #pragma unroll
            for (int ni = 0; ni < 4; ++ni) {
                int r = wn + ni * 8 + g;
                bfr[ni][0] = *(unsigned*)&vt[r][kb + 2 * tig];
                bfr[ni][1] = *(unsigned*)&vt[r][kb + 2 * tig + 8];
            }
            #pragma unroll
            for (int mi = 0; mi < 2; ++mi)
                #pragma unroll
                for (int ni = 0; ni < 4; ++ni)
                    mma_f16(acc[mi][ni][0], acc[mi][ni][1], acc[mi][ni][2], acc[mi][ni][3],
                            a[mi][0], a[mi][1], a[mi][2], a[mi][3], bfr[ni][0], bfr[ni][1]);
        }
        __syncthreads();
    }

    const float vsc = g_scales[2];
    #pragma unroll
    for (int mi = 0; mi < 2; ++mi) {
        int s = i0 + wm + mi * 16 + g;
        #pragma unroll
        for (int ni = 0; ni < 4; ++ni) {
            int d = wn + ni * 8 + 2 * tig;
            float2 v0 = {acc[mi][ni][0] * vsc, acc[mi][ni][1] * vsc};
            float2 v1 = {acc[mi][ni][2] * vsc, acc[mi][ni][3] * vsc};
            *(float2*)&g_attnout[(size_t)(b * S_ + s) * H_ + h * HD + d] = v0;
            *(float2*)&g_attnout[(size_t)(b * S_ + s + 8) * H_ + h * HD + d] = v1;
        }
    }
}

// ---------------- launch ----------------
extern "C" void kernel_launch(void* const* d_in, const int* in_sizes, int n_in,
                              void* d_out, int out_size)
{
    const float* x    = (const float*)d_in[0];
    const float* Wqkv = (const float*)d_in[1];
    const float* Wout = (const float*)d_in[2];
    const float* bout = (const float*)d_in[3];
    float* y = (float*)d_out;

    float *qkv_ptr = nullptr, *ao_ptr = nullptr;
    cudaGetSymbolAddress((void**)&qkv_ptr, g_qkv);
    cudaGetSymbolAddress((void**)&ao_ptr,  g_attnout);

    zero_kernel<<<1, 32>>>();

    // 1) qkv = x @ W_qkv
    sgemm128<<<dim3(H3 / 128, M1 / 128), 256>>>(x, Wqkv, qkv_ptr, M1, H3, H_, nullptr);

    // 2) per-tensor abs-max + scales
    absmax_kernel<<<1184, 256>>>();
    scales_kernel<<<1, 32>>>();

    // 3) quantize q/k/v to fp8 in head-major layout
    quant_kernel<<<(3 * PLANE) / 256, 256>>>();

    // 4) scores = q8 @ k8^T (fp16 MMA, exact) * qs*ks/sqrt(128)
    scores_mma_kernel<<<dim3(S_ / 128, S_ / 128, B_ * NH), 256>>>();

    // 5) softmax over keys
    softmax_kernel<<<B_ * NH * S_, 256>>>();

    // 6) out = (attn_f16 @ v8_f16) * v_scale  (fp16 MMA)
    pv_mma_kernel<<<dim3(S_ / 64, B_ * NH), 256>>>();

    // 7) y = out @ W_out + b_out
    sgemm128<<<dim3(H_ / 128, M1 / 128), 256>>>(ao_ptr, Wout, y, M1, H_, H_, bout);
}